// round 1
// baseline (speedup 1.0000x reference)
#include <cuda_runtime.h>
#include <stdint.h>

#define BB 16
#define NN 2048
#define KK 20
#define ROWS (BB * NN)

// ---- scratch (static __device__ — no allocations allowed) ----
__device__ float g_kval[ROWS * KK];
__device__ int   g_kidx[ROWS * KK];
__device__ float g_rowsum[ROWS];
__device__ float g_colsum[ROWS];
__device__ float g_dinv[ROWS];

// ---------------------------------------------------------------------------
__global__ void k_zero_colsum() {
    int i = blockIdx.x * blockDim.x + threadIdx.x;
    if (i < ROWS) g_colsum[i] = 0.0f;
}

// Warp-0 helper: given a 256-bin histogram, find digit d such that
// (#elements with digit > d) < kneed <= (#elements with digit >= d).
// Writes selected digit and updated kneed (rank within that bucket) to smem.
__device__ __forceinline__ void select_top_digit(const uint32_t* hist,
                                                 uint32_t kneed,
                                                 uint32_t* s_dsel,
                                                 uint32_t* s_kneed) {
    int lane = threadIdx.x;  // caller guarantees tid < 32
    uint32_t v[8];
    uint32_t lsum = 0;
#pragma unroll
    for (int j = 0; j < 8; j++) { v[j] = hist[lane * 8 + j]; lsum += v[j]; }
    // inclusive suffix-sum across lanes (lane l gets sum over lanes >= l)
    uint32_t suf = lsum;
#pragma unroll
    for (int off = 1; off < 32; off <<= 1) {
        uint32_t t = __shfl_down_sync(0xffffffffu, suf, off);
        if (lane + off < 32) suf += t;
    }
    uint32_t g = suf - lsum;  // count of elements in digits strictly above this lane's range
#pragma unroll
    for (int j = 7; j >= 0; j--) {
        uint32_t h = v[j];
        if (g < kneed && g + h >= kneed) {
            *s_dsel  = (uint32_t)(lane * 8 + j);
            *s_kneed = kneed - g;
        }
        g += h;
    }
}

// ---------------------------------------------------------------------------
// One block per row. Exact top-K (radix select over float bits of the doped
// scores, which are all >= 0 so uint ordering == float ordering). Emits the
// K kept (col, relu-value) pairs, the row sum, and atomic col-sum updates.
__global__ __launch_bounds__(256) void k_topk(const float* __restrict__ A,
                                              const float* __restrict__ Noise) {
    const int row = blockIdx.x;       // b * NN + i
    const int tid = threadIdx.x;
    const int b   = row >> 11;

    __shared__ uint32_t hist[256];
    __shared__ uint32_t candA[NN];
    __shared__ uint32_t candB[NN];
    __shared__ uint32_t s_cnt, s_cnt2, s_dsel, s_kneed, s_kslot, s_tiecnt;
    __shared__ float    s_rowsum;

    const float4* a4 = (const float4*)(A     + ((size_t)row << 11));
    const float4* n4 = (const float4*)(Noise + ((size_t)row << 11));

    float    rv[8];
    uint32_t db[8];
    int      cols[8];

    {
        float4 av  = a4[tid],       nv  = n4[tid];
        float4 av2 = a4[256 + tid], nv2 = n4[256 + tid];
        float aa[8] = {av.x, av.y, av.z, av.w, av2.x, av2.y, av2.z, av2.w};
        float no[8] = {nv.x, nv.y, nv.z, nv.w, nv2.x, nv2.y, nv2.z, nv2.w};
#pragma unroll
        for (int e = 0; e < 8; e++) {
            float r = fmaxf(aa[e], 0.0f);
            rv[e] = r;
            // forced non-contracted: doped = relu(a) + noise * 1e-4
            float d = __fadd_rn(r, __fmul_rn(no[e], 1e-4f));
            db[e] = __float_as_uint(d);
            cols[e] = (e < 4) ? (tid * 4 + e) : (1024 + tid * 4 + (e - 4));
        }
    }

    // ---- pass 1: histogram of top byte (from registers) ----
    hist[tid] = 0;
    if (tid == 0) { s_cnt = 0; s_rowsum = 0.0f; s_kslot = 0; }
    __syncthreads();
#pragma unroll
    for (int e = 0; e < 8; e++) atomicAdd(&hist[db[e] >> 24], 1u);
    __syncthreads();
    if (tid < 32) {
        select_top_digit(hist, KK, &s_dsel, &s_kneed);
    }
    __syncthreads();

    // compact matching elements into candA
    {
        uint32_t ds = s_dsel;
#pragma unroll
        for (int e = 0; e < 8; e++) {
            if ((db[e] >> 24) == ds) {
                uint32_t p = atomicAdd(&s_cnt, 1u);
                candA[p] = db[e];
            }
        }
    }
    __syncthreads();

    // ---- passes 2..4 over shrinking candidate list ----
    uint32_t* src = candA;
    uint32_t* dst = candB;
#pragma unroll
    for (int shift = 16; shift >= 0; shift -= 8) {
        hist[tid] = 0;
        if (tid == 0) s_cnt2 = 0;
        __syncthreads();
        uint32_t n = s_cnt;
        for (uint32_t i = tid; i < n; i += 256)
            atomicAdd(&hist[(src[i] >> shift) & 255u], 1u);
        __syncthreads();
        if (tid < 32) {
            uint32_t kn = s_kneed;
            __syncwarp();
            select_top_digit(hist, kn, &s_dsel, &s_kneed);
        }
        __syncthreads();
        uint32_t ds = s_dsel;
        for (uint32_t i = tid; i < n; i += 256) {
            uint32_t vv = src[i];
            if (((vv >> shift) & 255u) == ds) {
                uint32_t p = atomicAdd(&s_cnt2, 1u);
                dst[p] = vv;
            }
        }
        __syncthreads();
        if (tid == 0) s_cnt = s_cnt2;
        { uint32_t* t = src; src = dst; dst = t; }
        __syncthreads();
    }

    // src now holds all elements equal to the exact K-th largest value T.
    const uint32_t T       = src[0];
    const uint32_t tieCnt  = s_cnt;
    const uint32_t need    = s_kneed;   // how many ties to keep (lowest indices first)

    bool keep[8];
#pragma unroll
    for (int e = 0; e < 8; e++) keep[e] = (db[e] > T);

    if (need >= tieCnt) {
        // keep all ties (common case: 1 tie, need 1)
#pragma unroll
        for (int e = 0; e < 8; e++) keep[e] = keep[e] || (db[e] == T);
    } else {
        // collect tie column indices, break ties by lowest index (jax semantics)
        if (tid == 0) s_tiecnt = 0;
        __syncthreads();
#pragma unroll
        for (int e = 0; e < 8; e++) {
            if (db[e] == T) {
                uint32_t p = atomicAdd(&s_tiecnt, 1u);
                dst[p] = (uint32_t)cols[e];
            }
        }
        __syncthreads();
        uint32_t tc = s_tiecnt;
#pragma unroll
        for (int e = 0; e < 8; e++) {
            if (db[e] == T) {
                uint32_t rank = 0;
                for (uint32_t q = 0; q < tc; q++)
                    if (dst[q] < (uint32_t)cols[e]) rank++;
                keep[e] = keep[e] || (rank < need);
            }
        }
    }

    // ---- emit kept entries, row sum, column-sum atomics ----
    float myrs = 0.0f;
#pragma unroll
    for (int e = 0; e < 8; e++) {
        if (keep[e]) {
            uint32_t p = atomicAdd(&s_kslot, 1u);
            if (p < KK) {
                g_kidx[row * KK + p] = cols[e];
                g_kval[row * KK + p] = rv[e];
            }
            myrs += rv[e];
            atomicAdd(&g_colsum[b * NN + cols[e]], rv[e]);
        }
    }
    atomicAdd(&s_rowsum, myrs);
    __syncthreads();
    if (tid == 0) g_rowsum[row] = s_rowsum;
}

// ---------------------------------------------------------------------------
__global__ void k_dinv() {
    int i = blockIdx.x * blockDim.x + threadIdx.x;
    if (i < ROWS)
        g_dinv[i] = rsqrtf(fmaf(0.5f, g_rowsum[i] + g_colsum[i], 1.0f));
}

// ---------------------------------------------------------------------------
// out was memset to 0. Scatter: for each kept S_ij = v,
//   out[i][j] += 0.5*v*di*dj ; out[j][i] += 0.5*v*di*dj ; plus diagonal di^2.
__global__ void k_scatter(float* __restrict__ out) {
    int t = blockIdx.x * blockDim.x + threadIdx.x;
    if (t >= ROWS * KK) return;
    int row = t / KK;
    int k   = t - row * KK;
    int b   = row >> 11;
    int i   = row & (NN - 1);
    float di = g_dinv[row];
    int   j  = g_kidx[t];
    float v  = g_kval[t];
    float w  = 0.5f * v * di * g_dinv[b * NN + j];
    float* obase = out + ((size_t)b << 22);
    atomicAdd(obase + (size_t)i * NN + j, w);
    atomicAdd(obase + (size_t)j * NN + i, w);
    if (k == 0) atomicAdd(obase + (size_t)i * NN + i, di * di);
}

// ---------------------------------------------------------------------------
extern "C" void kernel_launch(void* const* d_in, const int* in_sizes, int n_in,
                              void* d_out, int out_size) {
    const float* A     = (const float*)d_in[0];
    const float* Noise = (const float*)d_in[1];
    float* out = (float*)d_out;

    k_zero_colsum<<<(ROWS + 255) / 256, 256>>>();
    k_topk<<<ROWS, 256>>>(A, Noise);
    k_dinv<<<(ROWS + 255) / 256, 256>>>();
    cudaMemsetAsync(d_out, 0, (size_t)out_size * sizeof(float));
    k_scatter<<<(ROWS * KK + 255) / 256, 256>>>(out);
}

// round 2
// speedup vs baseline: 1.5033x; 1.5033x over previous
#include <cuda_runtime.h>
#include <stdint.h>

#define BB 16
#define NN 2048
#define KK 20
#define ROWS (BB * NN)

// ---- scratch (static __device__ — no allocations allowed) ----
__device__ float g_kval[ROWS * KK];
__device__ int   g_kidx[ROWS * KK];
__device__ float g_rowsum[ROWS];
__device__ float g_colsum[ROWS];

// ---------------------------------------------------------------------------
__global__ void k_zero_colsum() {
    int i = blockIdx.x * blockDim.x + threadIdx.x;
    if (i < ROWS) g_colsum[i] = 0.0f;
}

// ---------------------------------------------------------------------------
// One block per row. Exact top-K via threshold pre-filter + rank-count among
// the survivors. Doped scores are >= 0 so uint bit-ordering == float ordering.
// Key packs (doped_bits, 2047-col) so rank-count reproduces jax.lax.top_k's
// lowest-index tie-break exactly. Fallback lowers the threshold (finally to
// accept-all) so exactness holds for any input.
__global__ __launch_bounds__(256) void k_topk(const float* __restrict__ A,
                                              const float* __restrict__ Noise) {
    const int row = blockIdx.x;       // b * NN + i
    const int tid = threadIdx.x;
    const int b   = row >> 11;

    __shared__ uint64_t candK[NN];    // (doped bits << 11) | (2047 - col)
    __shared__ float    candR[NN];    // relu value
    __shared__ uint32_t s_cnt, s_kslot;
    __shared__ float    s_rowsum;

    const float4* a4 = (const float4*)(A     + ((size_t)row << 11));
    const float4* n4 = (const float4*)(Noise + ((size_t)row << 11));

    float    rv[8];
    uint32_t db[8];
    int      cols[8];

    {
        float4 av  = a4[tid],       nv  = n4[tid];
        float4 av2 = a4[256 + tid], nv2 = n4[256 + tid];
        float aa[8] = {av.x, av.y, av.z, av.w, av2.x, av2.y, av2.z, av2.w};
        float no[8] = {nv.x, nv.y, nv.z, nv.w, nv2.x, nv2.y, nv2.z, nv2.w};
#pragma unroll
        for (int e = 0; e < 8; e++) {
            float r = fmaxf(aa[e], 0.0f);
            rv[e] = r;
            // match jax rounding: relu(a) + noise * 1e-4, round each step
            float d = __fadd_rn(r, __fmul_rn(no[e], 1e-4f));
            db[e] = __float_as_uint(d);
            cols[e] = (e < 4) ? (tid * 4 + e) : (1024 + tid * 4 + (e - 4));
        }
    }

    // ---- threshold pre-filter with fallback levels ----
    const uint32_t levels[3] = {
        __float_as_uint(1.8f), __float_as_uint(0.8f), __float_as_uint(0.2f)
    };
    uint32_t M;
    for (int lv = 0; lv < 4; lv++) {
        if (tid == 0) { s_cnt = 0; s_kslot = 0; s_rowsum = 0.0f; }
        __syncthreads();
        const bool all = (lv == 3);
        const uint32_t T = all ? 0u : levels[lv];
#pragma unroll
        for (int e = 0; e < 8; e++) {
            if (all || db[e] > T) {
                uint32_t p = atomicAdd(&s_cnt, 1u);
                candK[p] = ((uint64_t)db[e] << 11) | (uint64_t)(2047 - cols[e]);
                candR[p] = rv[e];
            }
        }
        __syncthreads();
        M = s_cnt;
        if (M >= KK) break;   // uniform: all threads read same smem value
    }

    // ---- exact rank-count among candidates; keep rank < K ----
    for (uint32_t i = tid; i < M; i += 256) {
        const uint64_t key = candK[i];
        uint32_t rank = 0;
        for (uint32_t q = 0; q < M; q++)
            rank += (candK[q] > key);
        if (rank < KK) {
            int col = 2047 - (int)(key & 2047u);
            float r = candR[i];
            uint32_t p = atomicAdd(&s_kslot, 1u);
            g_kidx[row * KK + p] = col;
            g_kval[row * KK + p] = r;
            atomicAdd(&s_rowsum, r);
            atomicAdd(&g_colsum[b * NN + col], r);
        }
    }
    __syncthreads();
    if (tid == 0) g_rowsum[row] = s_rowsum;
}

// ---------------------------------------------------------------------------
// out was memset to 0. For each kept S_ij = v:
//   w = 0.5*v*di*dj ; out[i][j] += w ; out[j][i] += w ; plus diagonal di^2.
// dinv computed inline: rsqrt(1 + 0.5*(rowsum+colsum)).
__global__ void k_scatter(float* __restrict__ out) {
    int t = blockIdx.x * blockDim.x + threadIdx.x;
    if (t >= ROWS * KK) return;
    int row = t / KK;
    int k   = t - row * KK;
    int b   = row >> 11;
    int i   = row & (NN - 1);
    float di = rsqrtf(fmaf(0.5f, g_rowsum[row] + g_colsum[row], 1.0f));
    int   j  = g_kidx[t];
    int   rj = b * NN + j;
    float dj = rsqrtf(fmaf(0.5f, g_rowsum[rj] + g_colsum[rj], 1.0f));
    float v  = g_kval[t];
    float w  = 0.5f * v * di * dj;
    float* obase = out + ((size_t)b << 22);
    atomicAdd(obase + (size_t)i * NN + j, w);
    atomicAdd(obase + (size_t)j * NN + i, w);
    if (k == 0) atomicAdd(obase + (size_t)i * NN + i, di * di);
}

// ---------------------------------------------------------------------------
extern "C" void kernel_launch(void* const* d_in, const int* in_sizes, int n_in,
                              void* d_out, int out_size) {
    const float* A     = (const float*)d_in[0];
    const float* Noise = (const float*)d_in[1];
    float* out = (float*)d_out;

    k_zero_colsum<<<(ROWS + 255) / 256, 256>>>();
    k_topk<<<ROWS, 256>>>(A, Noise);
    cudaMemsetAsync(d_out, 0, (size_t)out_size * sizeof(float));
    k_scatter<<<(ROWS * KK + 255) / 256, 256>>>(out);
}